// round 15
// baseline (speedup 1.0000x reference)
#include <cuda_runtime.h>
#include <math.h>

// ---------------------------------------------------------------------------
// BboxLoss (CIoU + DFL), B=32, A=8400, RM=16, NC=80.
// R15: R13 chassis (256thr x 592 blocks, block queue, depth-2 pipeline,
// pre-barrier prime, speculative bool compact) with straight-line staging:
// fixed per-lane cp.async assignment (<=5 transfers, constant offsets)
// replaces the 5-round predicate-chain dispatch -> ~2x fewer issue-side
// instructions per staged anchor.
// ---------------------------------------------------------------------------

#define EPSF 1e-7f
#define FOUR_OVER_PI2 0.40528473456935108577f   // 4 / pi^2
#define L2E 1.4426950408889634074f              // log2(e)
#define LN2 0.69314718055994530942f             // ln(2)
#define RM 16
#define NC 80

#define NBLOCKS 592
#define NTHREADS 256
#define NWARPS (NTHREADS / 32)
#define ANCH_F 168                               // 672B per staged anchor
#define QCAP_BLK 512                             // max slice = 114*4 = 456

__device__ double       g_acc[2];
__device__ unsigned int g_flags;
__device__ int          g_nfg_i;
__device__ unsigned int g_ticket;

struct __align__(128) PadCtr { unsigned int v; unsigned int pad[31]; };
__device__ PadCtr g_arrive;
__device__ PadCtr g_release;

__device__ __forceinline__ void cp16(unsigned int s, const void* g) {
    asm volatile("cp.async.cg.shared.global [%0], [%1], 16;" :: "r"(s), "l"(g));
}
__device__ __forceinline__ void cp8(unsigned int s, const void* g) {
    asm volatile("cp.async.ca.shared.global [%0], [%1], 8;" :: "r"(s), "l"(g));
}
__device__ __forceinline__ void cp_commit() {
    asm volatile("cp.async.commit_group;" ::: "memory");
}
template<int N> __device__ __forceinline__ void cp_wait_group() {
    asm volatile("cp.async.wait_group %0;" :: "n"(N) : "memory");
}
__device__ __forceinline__ void cp_wait_all() {
    asm volatile("cp.async.wait_all;" ::: "memory");
}

// Monotonic-epoch grid barrier; pollers spin on a read-only release flag.
__device__ __forceinline__ void grid_barrier()
{
    __syncthreads();
    if (threadIdx.x == 0) {
        __threadfence();
        unsigned int old   = atomicAdd(&g_arrive.v, 1u);
        unsigned int epoch = old / NBLOCKS + 1u;
        if (old % NBLOCKS == NBLOCKS - 1u) {
            atomicMax(&g_release.v, epoch);
        } else {
            while ((int)(*(volatile unsigned int*)&g_release.v - epoch) < 0)
                __nanosleep(40);
        }
    }
    __syncthreads();
    __threadfence();
}

__global__ __launch_bounds__(NTHREADS, 4)
void fused_bbox_loss(const float* __restrict__ pred_dist,
                     const float* __restrict__ pred_bboxes,
                     const float* __restrict__ anchor_points,
                     const float* __restrict__ target_bboxes,
                     const float* __restrict__ target_scores,
                     const float* __restrict__ tss,
                     const void*  __restrict__ fg_mask,
                     float*       __restrict__ out,
                     int nwords, int A, int out_size)
{
    const int lane = threadIdx.x & 31;
    const int wid  = threadIdx.x >> 5;
    const unsigned int FULL = 0xffffffffu;

    __shared__ __align__(16) float stage[NWARPS][8][ANCH_F];   // 43 KB
    __shared__ int sh_queue[QCAP_BLK];                         // 2 KB
    __shared__ int sh_wcnt[NWARPS];
    __shared__ int sh_cnt_blk;
    __shared__ double s0[NWARPS], s1[NWARPS];

    const int group = lane >> 3;
    const int gl    = lane & 7;

    // straight-line staging: fixed per-lane transfer assignment.
    // layout (bytes): [0,320) scores, [320,576) dist, [576,592) tgt box,
    // [592,608) pred box, [608,616) anchor point.
    auto issue_anchor = [&](int k, int n) {
        const char* srow = (const char*)target_scores + (size_t)n * 320;
        const char* drow = (const char*)pred_dist + (size_t)n * 256;
        unsigned int sb = (unsigned int)__cvta_generic_to_shared(
                              &stage[wid][k][0]);
        const int o = gl * 16;
        cp16(sb + o,         srow + o);            // scores chunk gl
        cp16(sb + 128 + o,   srow + 128 + o);      // scores chunk gl+8
        if (gl < 4) cp16(sb + 256 + o, srow + 256 + o);  // chunk gl+16
        cp16(sb + 320 + o,   drow + o);            // dist chunk gl
        cp16(sb + 448 + o,   drow + 128 + o);      // dist chunk gl+8
        if (gl == 4) cp16(sb + 576, (const char*)target_bboxes + (size_t)n * 16);
        if (gl == 5) cp16(sb + 592, (const char*)pred_bboxes + (size_t)n * 16);
        if (gl == 6) cp8(sb + 608, (const char*)anchor_points + (size_t)(n % A) * 8);
    };

    // issue round r (slots r*32 + wid*4 + group) into bank
    auto issue_round = [&](int r, int bank, int cnt_blk) {
        const int slot = r * (NWARPS * 4) + wid * 4 + group;
        if (slot < cnt_blk) issue_anchor(bank * 4 + group, sh_queue[slot]);
    };

    // ====== ONE mask pass: dtype flags + bool-speculative block queue ======
    const int wpb = (nwords + NBLOCKS - 1) / NBLOCKS;          // 114 here

    auto build_queue = [&](int mode) {
        int widx = blockIdx.x * wpb + wid + NWARPS * lane;
        bool in_range = (wid + NWARPS * lane < wpb) && (widx < nwords);

        int f0 = 0, f1 = 0, f2 = 0, f3 = 0;
        if (mode == 2) {
            unsigned int v = in_range ? ((const unsigned int*)fg_mask)[widx] : 0u;
            // dtype flags from the same read (grid collectively covers all)
            unsigned int f = 0u;
            if (v != 0u) f |= 1u;
            if (v > 1u)  f |= 2u;
            float xf = __uint_as_float(v);
            if (!(xf == 0.0f || xf == 1.0f)) f |= 4u;
            #pragma unroll
            for (int o = 16; o; o >>= 1) f |= __shfl_xor_sync(FULL, f, o);
            if (lane == 0 && f) atomicOr(&g_flags, f);

            f0 = (v & 0x000000ffu) != 0;
            f1 = (v & 0x0000ff00u) != 0;
            f2 = (v & 0x00ff0000u) != 0;
            f3 = (v & 0xff000000u) != 0;
        } else if (mode == 0) {
            if (in_range) {
                int4 v = ((const int4*)fg_mask)[widx];
                f0 = v.x != 0; f1 = v.y != 0; f2 = v.z != 0; f3 = v.w != 0;
            }
        } else {
            if (in_range) {
                float4 v = ((const float4*)fg_mask)[widx];
                f0 = v.x != 0.f; f1 = v.y != 0.f; f2 = v.z != 0.f; f3 = v.w != 0.f;
            }
        }
        int cntl = f0 + f1 + f2 + f3;
        int inc = cntl;
        #pragma unroll
        for (int o = 1; o < 32; o <<= 1) {
            int t = __shfl_up_sync(FULL, inc, o);
            if (lane >= o) inc += t;
        }
        if (lane == 31) sh_wcnt[wid] = inc;
        __syncthreads();
        if (threadIdx.x == 0) {
            int run = 0;
            #pragma unroll
            for (int w = 0; w < NWARPS; w++) {
                int t = sh_wcnt[w]; sh_wcnt[w] = run; run += t;
            }
            sh_cnt_blk = min(run, QCAP_BLK);
        }
        __syncthreads();

        int off = sh_wcnt[wid] + inc - cntl;
        int n = widx << 2;
        if (f0 && off < QCAP_BLK) sh_queue[off++] = n + 0;
        if (f1 && off < QCAP_BLK) sh_queue[off++] = n + 1;
        if (f2 && off < QCAP_BLK) sh_queue[off++] = n + 2;
        if (f3 && off < QCAP_BLK) sh_queue[off++] = n + 3;
        __syncthreads();
    };

    build_queue(2);                 // speculative: bool bytes
    int cnt_blk = sh_cnt_blk;

    // ====== prime pipeline: rounds 0,1 issued BEFORE the barrier ===========
    // (2 rounds x 32 anchors = 64 >= cnt_blk for ~99% of blocks: effectively
    // all data is draining while the barrier resolves)
    issue_round(0, 0, cnt_blk); cp_commit();
    issue_round(1, 1, cnt_blk); cp_commit();

    grid_barrier();

    // ====== mode resolution ================================================
    const unsigned int fl = *(volatile unsigned int*)&g_flags;
    int mode;                       // 0 = int32, 1 = float32, 2 = bool bytes
    if (!(fl & 1u))      mode = 2;
    else if (!(fl & 2u)) mode = 0;
    else if (!(fl & 4u)) mode = 1;
    else                 mode = 2;

    if (mode != 2) {                // rare path: rebuild + re-prime
        cp_wait_all();
        __syncthreads();
        build_queue(mode);
        cnt_blk = sh_cnt_blk;
        issue_round(0, 0, cnt_blk); cp_commit();
        issue_round(1, 1, cnt_blk); cp_commit();
    }

    // ====== pipelined compute ==============================================
    double acc_iou = 0.0, acc_dfl = 0.0;

    auto compute_bank = [&](int bank, bool act) {
        const float* S = &stage[wid][bank * 4 + group][0];

        float4 sq0 = *(const float4*)(S + gl * 4);
        float4 sq1 = *(const float4*)(S + 32 + gl * 4);
        float4 sq2 = (gl < 4) ? *(const float4*)(S + 64 + gl * 4)
                              : make_float4(0, 0, 0, 0);
        float ws = ((sq0.x + sq0.y) + (sq0.z + sq0.w))
                 + ((sq1.x + sq1.y) + (sq1.z + sq1.w))
                 + ((sq2.x + sq2.y) + (sq2.z + sq2.w));
        ws += __shfl_xor_sync(FULL, ws, 1, 8);
        ws += __shfl_xor_sync(FULL, ws, 2, 8);
        ws += __shfl_xor_sync(FULL, ws, 4, 8);

        float4 dq0 = *(const float4*)(S + 80 + gl * 8);
        float4 dq1 = *(const float4*)(S + 84 + gl * 8);
        float y[8];
        y[0] = dq0.x * L2E; y[1] = dq0.y * L2E;
        y[2] = dq0.z * L2E; y[3] = dq0.w * L2E;
        y[4] = dq1.x * L2E; y[5] = dq1.y * L2E;
        y[6] = dq1.z * L2E; y[7] = dq1.w * L2E;
        float m = y[0];
        #pragma unroll
        for (int kk = 1; kk < 8; kk++) m = fmaxf(m, y[kk]);
        m = fmaxf(m, __shfl_xor_sync(FULL, m, 1, 2));
        float se = 0.0f;
        #pragma unroll
        for (int kk = 0; kk < 8; kk++) se += exp2f(y[kk] - m);
        se += __shfl_xor_sync(FULL, se, 1, 2);
        float logZ2 = m + log2f(se);

        float4 bt  = *(const float4*)(S + 144);
        float2 apt = *(const float2*)(S + 152);
        const int s = gl >> 1;
        float t = (s == 0) ? (apt.x - bt.x)
                : (s == 1) ? (apt.y - bt.y)
                : (s == 2) ? (bt.z - apt.x)
                :            (bt.w - apt.y);
        t = fminf(fmaxf(t, 0.0f), (float)(RM - 1) - 0.01f);
        const int   tl = (int)t;
        const int   tr = min(tl + 1, RM - 1);
        const float wl = (float)(tl + 1) - t;
        const float wr = 1.0f - wl;

        const int bofs = (gl & 1) * 8;
        float yl = 0.0f, yr = 0.0f;
        #pragma unroll
        for (int kk = 0; kk < 8; kk++) {
            yl = (tl - bofs == kk) ? y[kk] : yl;
            yr = (tr - bofs == kk) ? y[kk] : yr;
        }
        yl += __shfl_xor_sync(FULL, yl, 1, 2);
        yr += __shfl_xor_sync(FULL, yr, 1, 2);

        float dfl2 = logZ2 - (yl * wl + yr * wr);
        float dc = (((gl & 1) == 0) && act) ? dfl2 : 0.0f;
        dc += __shfl_xor_sync(FULL, dc, 2, 8);
        dc += __shfl_xor_sync(FULL, dc, 4, 8);

        if (gl == 0 && act) {
            float4 bp = *(const float4*)(S + 148);
            float x11 = bp.x, y11 = bp.y, x21 = bp.z, y21 = bp.w;
            float x12 = bt.x, y12 = bt.y, x22 = bt.z, y22 = bt.w;
            float iw = fmaxf(fminf(x21, x22) - fmaxf(x11, x12), 0.f);
            float ih = fmaxf(fminf(y21, y22) - fmaxf(y11, y12), 0.f);
            float inter = iw * ih;
            float w1 = x21 - x11, h1 = y21 - y11;
            float w2 = x22 - x12, h2 = y22 - y12;
            float uni = w1 * h1 + w2 * h2 - inter + EPSF;
            float iou = __fdividef(inter, uni);
            float cw = fmaxf(x21, x22) - fminf(x11, x12);
            float ch = fmaxf(y21, y22) - fminf(y11, y12);
            float c2 = cw * cw + ch * ch + EPSF;
            float dx = x11 + x21 - x12 - x22;
            float dy = y11 + y21 - y12 - y22;
            float rho2 = (dx * dx + dy * dy) * 0.25f;
            float dat = atanf(__fdividef(w1, h1 + EPSF))
                      - atanf(__fdividef(w2, h2 + EPSF));
            float v = FOUR_OVER_PI2 * dat * dat;
            float alpha = __fdividef(v, 1.0f - iou + v + EPSF);
            float ciou = iou - (__fdividef(rho2, c2) + v * alpha);

            acc_iou += (double)((1.0f - ciou) * ws);
            acc_dfl += (double)dc;              // base-2 units
        }
    };

    const int quantum = NWARPS * 4;             // 32 anchors per round
    const int rounds = (cnt_blk + quantum - 1) / quantum;
    for (int r = 0; r < rounds; r++) {
        cp_wait_group<1>();                     // round r's bank is ready
        __syncwarp();
        const int slot = r * quantum + wid * 4 + group;
        compute_bank(r & 1, slot < cnt_blk);
        __syncwarp();
        issue_round(r + 2, r & 1, cnt_blk);     // refill the bank just used
        cp_commit();
    }
    cp_wait_all();                              // drain trailing groups

    // lanes 0,8,16,24 hold partials -> 2 shuffles to lane 0
    acc_iou += __shfl_xor_sync(FULL, acc_iou, 8);
    acc_iou += __shfl_xor_sync(FULL, acc_iou, 16);
    acc_dfl += __shfl_xor_sync(FULL, acc_dfl, 8);
    acc_dfl += __shfl_xor_sync(FULL, acc_dfl, 16);

    if (lane == 0) { s0[wid] = acc_iou; s1[wid] = acc_dfl; }
    __syncthreads();
    if (threadIdx.x == 0) {
        double a0 = 0, a1 = 0;
        #pragma unroll
        for (int i = 0; i < NWARPS; i++) { a0 += s0[i]; a1 += s1[i]; }
        if (a0 != 0.0) atomicAdd(&g_acc[0], a0);
        if (a1 != 0.0) atomicAdd(&g_acc[1], a1);
        if (cnt_blk)   atomicAdd(&g_nfg_i, cnt_blk);
        __threadfence();
        unsigned int old = atomicAdd(&g_ticket, 1u);
        if (old % NBLOCKS == NBLOCKS - 1u) {
            double si  = *(volatile double*)&g_acc[0];
            double sd  = *(volatile double*)&g_acc[1] * (double)LN2;
            double nfg = (double)(*(volatile int*)&g_nfg_i);
            double li = si / (double)tss[0];
            double ld = sd / fmax(nfg * 4.0, 1.0);
            if (out_size >= 1) out[0] = (float)li;
            if (out_size >= 2) out[1] = (float)ld;
            g_acc[0] = 0.0; g_acc[1] = 0.0;
            g_flags = 0u; g_nfg_i = 0;
        }
    }
}

// ---------------------------------------------------------------------------
// Launch. Inputs (metadata order): pred_dist, pred_bboxes, anchor_points,
// target_bboxes, target_scores, target_scores_sum, fg_mask.
// ---------------------------------------------------------------------------
extern "C" void kernel_launch(void* const* d_in, const int* in_sizes, int n_in,
                              void* d_out, int out_size)
{
    const float* pred_dist     = (const float*)d_in[0];
    const float* pred_bboxes   = (const float*)d_in[1];
    const float* anchor_points = (const float*)d_in[2];
    const float* target_bboxes = (const float*)d_in[3];
    const float* target_scores = (const float*)d_in[4];
    const float* tss           = (const float*)d_in[5];
    const void*  fg_mask       = (const void*)d_in[6];

    const int BA = in_sizes[6];
    const int A  = in_sizes[2] / 2;

    fused_bbox_loss<<<NBLOCKS, NTHREADS>>>(
        pred_dist, pred_bboxes, anchor_points, target_bboxes, target_scores,
        tss, fg_mask, (float*)d_out, BA >> 2, A, out_size);
}

// round 16
// speedup vs baseline: 1.3689x; 1.3689x over previous
#include <cuda_runtime.h>
#include <math.h>

// ---------------------------------------------------------------------------
// BboxLoss (CIoU + DFL), B=32, A=8400, RM=16, NC=80.
// R16 = revert to R13 (best measured: 20.99 us). Block-level fg queue
// (8-warp load balance) + depth-2 software pipeline over 4-anchor rounds
// (two stage banks; rounds 0/1 issued before the grid barrier so their
// drain overlaps the barrier wait; each later round's issue overlaps the
// previous round's compute). Idx-ordered staging loop (load-bearing for
// L1TEX wavefront order — do not "simplify", see R15 regression).
// ---------------------------------------------------------------------------

#define EPSF 1e-7f
#define FOUR_OVER_PI2 0.40528473456935108577f   // 4 / pi^2
#define L2E 1.4426950408889634074f              // log2(e)
#define LN2 0.69314718055994530942f             // ln(2)
#define RM 16
#define NC 80

#define NBLOCKS 592
#define NTHREADS 256
#define NWARPS (NTHREADS / 32)
#define ANCH_F 168                               // floats per staged anchor (672B)
#define QCAP_BLK 512                             // block queue (max slice = 456)

__device__ double       g_acc[2];
__device__ unsigned int g_flags;
__device__ int          g_nfg_i;
__device__ unsigned int g_ticket;

struct __align__(128) PadCtr { unsigned int v; unsigned int pad[31]; };
__device__ PadCtr g_arrive;
__device__ PadCtr g_release;

__device__ __forceinline__ void cp16(unsigned int s, const void* g) {
    asm volatile("cp.async.cg.shared.global [%0], [%1], 16;" :: "r"(s), "l"(g));
}
__device__ __forceinline__ void cp8(unsigned int s, const void* g) {
    asm volatile("cp.async.ca.shared.global [%0], [%1], 8;" :: "r"(s), "l"(g));
}
__device__ __forceinline__ void cp_commit() {
    asm volatile("cp.async.commit_group;" ::: "memory");
}
template<int N> __device__ __forceinline__ void cp_wait_group() {
    asm volatile("cp.async.wait_group %0;" :: "n"(N) : "memory");
}
__device__ __forceinline__ void cp_wait_all() {
    asm volatile("cp.async.wait_all;" ::: "memory");
}

// Monotonic-epoch grid barrier; pollers spin on a read-only release flag.
__device__ __forceinline__ void grid_barrier()
{
    __syncthreads();
    if (threadIdx.x == 0) {
        __threadfence();
        unsigned int old   = atomicAdd(&g_arrive.v, 1u);
        unsigned int epoch = old / NBLOCKS + 1u;
        if (old % NBLOCKS == NBLOCKS - 1u) {
            atomicMax(&g_release.v, epoch);
        } else {
            while ((int)(*(volatile unsigned int*)&g_release.v - epoch) < 0)
                __nanosleep(40);
        }
    }
    __syncthreads();
    __threadfence();
}

__global__ __launch_bounds__(NTHREADS, 4)
void fused_bbox_loss(const float* __restrict__ pred_dist,
                     const float* __restrict__ pred_bboxes,
                     const float* __restrict__ anchor_points,
                     const float* __restrict__ target_bboxes,
                     const float* __restrict__ target_scores,
                     const float* __restrict__ tss,
                     const void*  __restrict__ fg_mask,
                     float*       __restrict__ out,
                     int nwords, int A, int out_size)
{
    const int lane = threadIdx.x & 31;
    const int wid  = threadIdx.x >> 5;
    const unsigned int FULL = 0xffffffffu;

    __shared__ __align__(16) float stage[NWARPS][8][ANCH_F];   // 43 KB
    __shared__ int sh_queue[QCAP_BLK];                         // 2 KB
    __shared__ int sh_wcnt[NWARPS];
    __shared__ int sh_cnt_blk;
    __shared__ double s0[NWARPS], s1[NWARPS];

    const int group = lane >> 3;
    const int gl    = lane & 7;

    // issue the 39 cp.asyncs for anchor n into this warp's stage slot k
    // (idx-ordered 5-round loop: consecutive issues cover consecutive 128B
    //  global segments — load-bearing for L1TEX wavefront order)
    auto issue_anchor = [&](int k, int n) {
        const char* srow = (const char*)(target_scores + (size_t)n * NC);
        const char* drow = (const char*)(pred_dist + (size_t)n * (4 * RM));
        unsigned int sb = (unsigned int)__cvta_generic_to_shared(
                              &stage[wid][k][0]);
        #pragma unroll
        for (int rr = 0; rr < 5; rr++) {
            int idx = rr * 8 + gl;
            if (idx < 20) {
                cp16(sb + idx * 16, srow + idx * 16);
            } else if (idx < 36) {
                cp16(sb + 320 + (idx - 20) * 16, drow + (idx - 20) * 16);
            } else if (idx == 36) {
                cp16(sb + 576, (const char*)target_bboxes + (size_t)n * 16);
            } else if (idx == 37) {
                cp16(sb + 592, (const char*)pred_bboxes + (size_t)n * 16);
            } else if (idx == 38) {
                cp8(sb + 608, (const char*)anchor_points + (size_t)(n % A) * 8);
            }
        }
    };

    // issue round r (4 anchors: slot r*32 + wid*4 + group) into bank
    auto issue_round = [&](int r, int bank, int cnt_blk) {
        const int slot = r * 32 + wid * 4 + group;
        if (slot < cnt_blk) issue_anchor(bank * 4 + group, sh_queue[slot]);
    };

    // ====== ONE mask pass: dtype flags + bool-speculative block queue ======
    // Block owns words [blk*wpb, blk*wpb+wpb); warp w reads words
    // {blk*wpb + w + 8k}, lane l handles k=l.
    const int wpb = (nwords + NBLOCKS - 1) / NBLOCKS;

    auto build_queue = [&](int mode) {
        int widx = blockIdx.x * wpb + wid + 8 * lane;
        bool in_range = (wid + 8 * lane < wpb) && (widx < nwords);

        int f0 = 0, f1 = 0, f2 = 0, f3 = 0;
        if (mode == 2) {
            unsigned int v = in_range ? ((const unsigned int*)fg_mask)[widx] : 0u;
            // dtype flags from the same read (grid collectively covers all)
            unsigned int f = 0u;
            if (v != 0u) f |= 1u;
            if (v > 1u)  f |= 2u;
            float xf = __uint_as_float(v);
            if (!(xf == 0.0f || xf == 1.0f)) f |= 4u;
            #pragma unroll
            for (int o = 16; o; o >>= 1) f |= __shfl_xor_sync(FULL, f, o);
            if (lane == 0 && f) atomicOr(&g_flags, f);

            f0 = (v & 0x000000ffu) != 0;
            f1 = (v & 0x0000ff00u) != 0;
            f2 = (v & 0x00ff0000u) != 0;
            f3 = (v & 0xff000000u) != 0;
        } else if (mode == 0) {
            if (in_range) {
                int4 v = ((const int4*)fg_mask)[widx];
                f0 = v.x != 0; f1 = v.y != 0; f2 = v.z != 0; f3 = v.w != 0;
            }
        } else {
            if (in_range) {
                float4 v = ((const float4*)fg_mask)[widx];
                f0 = v.x != 0.f; f1 = v.y != 0.f; f2 = v.z != 0.f; f3 = v.w != 0.f;
            }
        }
        int cntl = f0 + f1 + f2 + f3;
        int inc = cntl;
        #pragma unroll
        for (int o = 1; o < 32; o <<= 1) {
            int t = __shfl_up_sync(FULL, inc, o);
            if (lane >= o) inc += t;
        }
        if (lane == 31) sh_wcnt[wid] = inc;
        __syncthreads();
        if (threadIdx.x == 0) {
            int run = 0;
            #pragma unroll
            for (int w = 0; w < NWARPS; w++) {
                int t = sh_wcnt[w]; sh_wcnt[w] = run; run += t;
            }
            sh_cnt_blk = min(run, QCAP_BLK);
        }
        __syncthreads();

        int off = sh_wcnt[wid] + inc - cntl;
        int n = widx << 2;
        if (f0 && off < QCAP_BLK) sh_queue[off++] = n + 0;
        if (f1 && off < QCAP_BLK) sh_queue[off++] = n + 1;
        if (f2 && off < QCAP_BLK) sh_queue[off++] = n + 2;
        if (f3 && off < QCAP_BLK) sh_queue[off++] = n + 3;
        __syncthreads();
    };

    build_queue(2);                 // speculative: bool bytes
    int cnt_blk = sh_cnt_blk;

    // ====== prime pipeline: rounds 0,1 issued BEFORE the barrier ===========
    issue_round(0, 0, cnt_blk); cp_commit();
    issue_round(1, 1, cnt_blk); cp_commit();

    grid_barrier();

    // ====== mode resolution ================================================
    const unsigned int fl = *(volatile unsigned int*)&g_flags;
    int mode;                       // 0 = int32, 1 = float32, 2 = bool bytes
    if (!(fl & 1u))      mode = 2;
    else if (!(fl & 2u)) mode = 0;
    else if (!(fl & 4u)) mode = 1;
    else                 mode = 2;

    if (mode != 2) {                // rare path: rebuild + re-prime
        cp_wait_all();
        __syncthreads();
        build_queue(mode);
        cnt_blk = sh_cnt_blk;
        issue_round(0, 0, cnt_blk); cp_commit();
        issue_round(1, 1, cnt_blk); cp_commit();
    }

    // ====== pipelined compute ==============================================
    double acc_iou = 0.0, acc_dfl = 0.0;

    auto compute_bank = [&](int bank, bool act) {
        const float* S = &stage[wid][bank * 4 + group][0];

        float4 sq0 = *(const float4*)(S + gl * 4);
        float4 sq1 = *(const float4*)(S + 32 + gl * 4);
        float4 sq2 = (gl < 4) ? *(const float4*)(S + 64 + gl * 4)
                              : make_float4(0, 0, 0, 0);
        float ws = ((sq0.x + sq0.y) + (sq0.z + sq0.w))
                 + ((sq1.x + sq1.y) + (sq1.z + sq1.w))
                 + ((sq2.x + sq2.y) + (sq2.z + sq2.w));
        ws += __shfl_xor_sync(FULL, ws, 1, 8);
        ws += __shfl_xor_sync(FULL, ws, 2, 8);
        ws += __shfl_xor_sync(FULL, ws, 4, 8);

        float4 dq0 = *(const float4*)(S + 80 + gl * 8);
        float4 dq1 = *(const float4*)(S + 84 + gl * 8);
        float y[8];
        y[0] = dq0.x * L2E; y[1] = dq0.y * L2E;
        y[2] = dq0.z * L2E; y[3] = dq0.w * L2E;
        y[4] = dq1.x * L2E; y[5] = dq1.y * L2E;
        y[6] = dq1.z * L2E; y[7] = dq1.w * L2E;
        float m = y[0];
        #pragma unroll
        for (int kk = 1; kk < 8; kk++) m = fmaxf(m, y[kk]);
        m = fmaxf(m, __shfl_xor_sync(FULL, m, 1, 2));
        float se = 0.0f;
        #pragma unroll
        for (int kk = 0; kk < 8; kk++) se += exp2f(y[kk] - m);
        se += __shfl_xor_sync(FULL, se, 1, 2);
        float logZ2 = m + log2f(se);

        float4 bt  = *(const float4*)(S + 144);
        float2 apt = *(const float2*)(S + 152);
        const int s = gl >> 1;
        float t = (s == 0) ? (apt.x - bt.x)
                : (s == 1) ? (apt.y - bt.y)
                : (s == 2) ? (bt.z - apt.x)
                :            (bt.w - apt.y);
        t = fminf(fmaxf(t, 0.0f), (float)(RM - 1) - 0.01f);
        const int   tl = (int)t;
        const int   tr = min(tl + 1, RM - 1);
        const float wl = (float)(tl + 1) - t;
        const float wr = 1.0f - wl;

        const int bofs = (gl & 1) * 8;
        float yl = 0.0f, yr = 0.0f;
        #pragma unroll
        for (int kk = 0; kk < 8; kk++) {
            yl = (tl - bofs == kk) ? y[kk] : yl;
            yr = (tr - bofs == kk) ? y[kk] : yr;
        }
        yl += __shfl_xor_sync(FULL, yl, 1, 2);
        yr += __shfl_xor_sync(FULL, yr, 1, 2);

        float dfl2 = logZ2 - (yl * wl + yr * wr);
        float dc = (((gl & 1) == 0) && act) ? dfl2 : 0.0f;
        dc += __shfl_xor_sync(FULL, dc, 2, 8);
        dc += __shfl_xor_sync(FULL, dc, 4, 8);

        if (gl == 0 && act) {
            float4 bp = *(const float4*)(S + 148);
            float x11 = bp.x, y11 = bp.y, x21 = bp.z, y21 = bp.w;
            float x12 = bt.x, y12 = bt.y, x22 = bt.z, y22 = bt.w;
            float iw = fmaxf(fminf(x21, x22) - fmaxf(x11, x12), 0.f);
            float ih = fmaxf(fminf(y21, y22) - fmaxf(y11, y12), 0.f);
            float inter = iw * ih;
            float w1 = x21 - x11, h1 = y21 - y11;
            float w2 = x22 - x12, h2 = y22 - y12;
            float uni = w1 * h1 + w2 * h2 - inter + EPSF;
            float iou = __fdividef(inter, uni);
            float cw = fmaxf(x21, x22) - fminf(x11, x12);
            float ch = fmaxf(y21, y22) - fminf(y11, y12);
            float c2 = cw * cw + ch * ch + EPSF;
            float dx = x11 + x21 - x12 - x22;
            float dy = y11 + y21 - y12 - y22;
            float rho2 = (dx * dx + dy * dy) * 0.25f;
            float dat = atanf(__fdividef(w1, h1 + EPSF))
                      - atanf(__fdividef(w2, h2 + EPSF));
            float v = FOUR_OVER_PI2 * dat * dat;
            float alpha = __fdividef(v, 1.0f - iou + v + EPSF);
            float ciou = iou - (__fdividef(rho2, c2) + v * alpha);

            acc_iou += (double)((1.0f - ciou) * ws);
            acc_dfl += (double)dc;              // base-2 units
        }
    };

    const int rounds = (cnt_blk + 31) >> 5;     // uniform across the block
    for (int r = 0; r < rounds; r++) {
        cp_wait_group<1>();                     // round r's bank is ready
        __syncwarp();
        const int slot = r * 32 + wid * 4 + group;
        compute_bank(r & 1, slot < cnt_blk);
        __syncwarp();
        issue_round(r + 2, r & 1, cnt_blk);     // refill the bank just used
        cp_commit();
    }
    cp_wait_all();                              // drain trailing empty groups

    // lanes 0,8,16,24 hold partials -> 2 shuffles to lane 0
    acc_iou += __shfl_xor_sync(FULL, acc_iou, 8);
    acc_iou += __shfl_xor_sync(FULL, acc_iou, 16);
    acc_dfl += __shfl_xor_sync(FULL, acc_dfl, 8);
    acc_dfl += __shfl_xor_sync(FULL, acc_dfl, 16);

    if (lane == 0) { s0[wid] = acc_iou; s1[wid] = acc_dfl; }
    __syncthreads();
    if (threadIdx.x == 0) {
        double a0 = 0, a1 = 0;
        #pragma unroll
        for (int i = 0; i < NWARPS; i++) { a0 += s0[i]; a1 += s1[i]; }
        if (a0 != 0.0) atomicAdd(&g_acc[0], a0);
        if (a1 != 0.0) atomicAdd(&g_acc[1], a1);
        if (cnt_blk)   atomicAdd(&g_nfg_i, cnt_blk);
        __threadfence();
        unsigned int old = atomicAdd(&g_ticket, 1u);
        if (old % NBLOCKS == NBLOCKS - 1u) {
            double si  = *(volatile double*)&g_acc[0];
            double sd  = *(volatile double*)&g_acc[1] * (double)LN2;
            double nfg = (double)(*(volatile int*)&g_nfg_i);
            double li = si / (double)tss[0];
            double ld = sd / fmax(nfg * 4.0, 1.0);
            if (out_size >= 1) out[0] = (float)li;
            if (out_size >= 2) out[1] = (float)ld;
            g_acc[0] = 0.0; g_acc[1] = 0.0;
            g_flags = 0u; g_nfg_i = 0;
        }
    }
}

// ---------------------------------------------------------------------------
// Launch. Inputs (metadata order): pred_dist, pred_bboxes, anchor_points,
// target_bboxes, target_scores, target_scores_sum, fg_mask.
// ---------------------------------------------------------------------------
extern "C" void kernel_launch(void* const* d_in, const int* in_sizes, int n_in,
                              void* d_out, int out_size)
{
    const float* pred_dist     = (const float*)d_in[0];
    const float* pred_bboxes   = (const float*)d_in[1];
    const float* anchor_points = (const float*)d_in[2];
    const float* target_bboxes = (const float*)d_in[3];
    const float* target_scores = (const float*)d_in[4];
    const float* tss           = (const float*)d_in[5];
    const void*  fg_mask       = (const void*)d_in[6];

    const int BA = in_sizes[6];
    const int A  = in_sizes[2] / 2;

    fused_bbox_loss<<<NBLOCKS, NTHREADS>>>(
        pred_dist, pred_bboxes, anchor_points, target_bboxes, target_scores,
        tss, fg_mask, (float*)d_out, BA >> 2, A, out_size);
}